// round 1
// baseline (speedup 1.0000x reference)
#include <cuda_runtime.h>
#include <cuda_bf16.h>

// Problem constants
#define NN   1024          // graph size
#define NN2  (NN * NN)
#define BD   64            // feature dim D
#define NB   128           // batch

// Tiling
#define BM   128
#define BN   128
#define BK   16
#define PAD  8             // As padding to avoid transposed-store bank conflicts
#define NSPLIT 4           // split-K factor for the 1024^3 GEMMs

// Scratch (allocation-free rule: __device__ globals)
__device__ float g_bufA[NN2];
__device__ float g_bufB[NN2];
__device__ float g_part[NSPLIT][NN2];

// ---------------------------------------------------------------------------
// GEMM with split-K:  g_part[bz] (tile) = A[rows, kslice] @ S[kslice, cols]
// A selected by aSel: 0 -> weight[7] (first Horner step), 1 -> g_bufA, 2 -> g_bufB
// ---------------------------------------------------------------------------
__global__ __launch_bounds__(256)
void gemm_splitk(int aSel, const float* __restrict__ weight,
                 const float* __restrict__ S) {
    __shared__ float As[BK][BM + PAD];
    __shared__ float Bs[BK][BN];

    const float* A = (aSel == 0) ? (weight + (size_t)7 * NN2)
                                 : (aSel == 1 ? g_bufA : g_bufB);

    const int tid   = threadIdx.x;
    const int row0  = blockIdx.y * BM;
    const int col0  = blockIdx.x * BN;
    const int kbase = blockIdx.z * (NN / NSPLIT);
    const int ty    = tid >> 4;   // 0..15
    const int tx    = tid & 15;   // 0..15

    float acc[8][8] = {};

    for (int kt = 0; kt < NN / NSPLIT; kt += BK) {
        // Load A tile [BM x BK], store transposed into As
        #pragma unroll
        for (int i = 0; i < 2; ++i) {
            int f = tid + i * 256;            // float4 index, 512 total
            int r = f >> 2;                   // 0..127
            int c = (f & 3) << 2;             // 0,4,8,12
            float4 v = *(const float4*)(A + (size_t)(row0 + r) * NN + kbase + kt + c);
            As[c + 0][r] = v.x;
            As[c + 1][r] = v.y;
            As[c + 2][r] = v.z;
            As[c + 3][r] = v.w;
        }
        // Load B tile [BK x BN]
        #pragma unroll
        for (int i = 0; i < 2; ++i) {
            int f  = tid + i * 256;
            int rb = f >> 5;                  // 0..15
            int cb = (f & 31) << 2;           // 0..124
            *(float4*)&Bs[rb][cb] =
                *(const float4*)(S + (size_t)(kbase + kt + rb) * NN + col0 + cb);
        }
        __syncthreads();

        #pragma unroll
        for (int k = 0; k < BK; ++k) {
            float a[8], b[8];
            *(float4*)&a[0] = *(const float4*)&As[k][ty * 4];
            *(float4*)&a[4] = *(const float4*)&As[k][64 + ty * 4];
            *(float4*)&b[0] = *(const float4*)&Bs[k][tx * 4];
            *(float4*)&b[4] = *(const float4*)&Bs[k][64 + tx * 4];
            #pragma unroll
            for (int i = 0; i < 8; ++i)
                #pragma unroll
                for (int j = 0; j < 8; ++j)
                    acc[i][j] += a[i] * b[j];
        }
        __syncthreads();
    }

    float* Cp = g_part[blockIdx.z];
    #pragma unroll
    for (int i = 0; i < 8; ++i) {
        int m = row0 + ((i < 4) ? (ty * 4 + i) : (64 + ty * 4 + i - 4));
        *(float4*)(Cp + (size_t)m * NN + col0 + tx * 4) =
            make_float4(acc[i][0], acc[i][1], acc[i][2], acc[i][3]);
        *(float4*)(Cp + (size_t)m * NN + col0 + 64 + tx * 4) =
            make_float4(acc[i][4], acc[i][5], acc[i][6], acc[i][7]);
    }
}

// ---------------------------------------------------------------------------
// out = sum(parts) + Wk   (Horner step epilogue)
// ---------------------------------------------------------------------------
__global__ void reduce_add(const float* __restrict__ Wk, int outSel) {
    float* out = (outSel == 1) ? g_bufA : g_bufB;
    size_t i = ((size_t)blockIdx.x * blockDim.x + threadIdx.x) * 4;
    float4 p0 = *(const float4*)&g_part[0][i];
    float4 p1 = *(const float4*)&g_part[1][i];
    float4 p2 = *(const float4*)&g_part[2][i];
    float4 p3 = *(const float4*)&g_part[3][i];
    float4 w  = *(const float4*)&Wk[i];
    float4 r;
    r.x = p0.x + p1.x + p2.x + p3.x + w.x;
    r.y = p0.y + p1.y + p2.y + p3.y + w.y;
    r.z = p0.z + p1.z + p2.z + p3.z + w.z;
    r.w = p0.w + p1.w + p2.w + p3.w + w.w;
    *(float4*)&out[i] = r;
}

// ---------------------------------------------------------------------------
// Final stage: out[b] = A @ X[b].  Each block: 128 rows x (2 batches x 64 d).
// A read from g_bufA. Grid: (64 batch-pairs, 8 row tiles).
// ---------------------------------------------------------------------------
__global__ __launch_bounds__(256)
void gemm_out(const float* __restrict__ X, float* __restrict__ O) {
    __shared__ float As[BK][BM + PAD];
    __shared__ float Bs[BK][BN];

    const int tid  = threadIdx.x;
    const int row0 = blockIdx.y * BM;
    const int b0   = blockIdx.x * 2;
    const int ty   = tid >> 4;
    const int tx   = tid & 15;

    float acc[8][8] = {};

    for (int kt = 0; kt < NN; kt += BK) {
        #pragma unroll
        for (int i = 0; i < 2; ++i) {
            int f = tid + i * 256;
            int r = f >> 2;
            int c = (f & 3) << 2;
            float4 v = *(const float4*)(g_bufA + (size_t)(row0 + r) * NN + kt + c);
            As[c + 0][r] = v.x;
            As[c + 1][r] = v.y;
            As[c + 2][r] = v.z;
            As[c + 3][r] = v.w;
        }
        #pragma unroll
        for (int i = 0; i < 2; ++i) {
            int f  = tid + i * 256;
            int rb = f >> 5;          // k-row within tile: 0..15
            int cb = f & 31;          // float4-col: 0..31
            int bb = cb >> 4;         // which batch of the pair
            int d4 = (cb & 15) << 2;  // d offset 0..60
            *(float4*)&Bs[rb][cb << 2] =
                *(const float4*)(X + ((size_t)(b0 + bb) * NN + kt + rb) * BD + d4);
        }
        __syncthreads();

        #pragma unroll
        for (int k = 0; k < BK; ++k) {
            float a[8], b[8];
            *(float4*)&a[0] = *(const float4*)&As[k][ty * 4];
            *(float4*)&a[4] = *(const float4*)&As[k][64 + ty * 4];
            *(float4*)&b[0] = *(const float4*)&Bs[k][tx * 4];
            *(float4*)&b[4] = *(const float4*)&Bs[k][64 + tx * 4];
            #pragma unroll
            for (int i = 0; i < 8; ++i)
                #pragma unroll
                for (int j = 0; j < 8; ++j)
                    acc[i][j] += a[i] * b[j];
        }
        __syncthreads();
    }

    #pragma unroll
    for (int i = 0; i < 8; ++i) {
        int m = row0 + ((i < 4) ? (ty * 4 + i) : (64 + ty * 4 + i - 4));
        // cols 0..63  -> batch b0,   d = tx*4 + j
        *(float4*)(O + ((size_t)b0 * NN + m) * BD + tx * 4) =
            make_float4(acc[i][0], acc[i][1], acc[i][2], acc[i][3]);
        // cols 64..127 -> batch b0+1, d = tx*4 + (j-4)
        *(float4*)(O + ((size_t)(b0 + 1) * NN + m) * BD + tx * 4) =
            make_float4(acc[i][4], acc[i][5], acc[i][6], acc[i][7]);
    }
}

// ---------------------------------------------------------------------------
// Horner: T = W7; for k = 6..0: T = Wk + T @ S;  then out[b] = T @ X[b]
// ---------------------------------------------------------------------------
extern "C" void kernel_launch(void* const* d_in, const int* in_sizes, int n_in,
                              void* d_out, int out_size) {
    const float* nodes  = (const float*)d_in[0];   // [128, 1024, 64]
    const float* weight = (const float*)d_in[1];   // [8, 1024, 1024]
    const float* S      = (const float*)d_in[2];   // [1024, 1024]
    float* out = (float*)d_out;                    // [128, 1024, 64]

    int inSel = 0;  // 0 = weight[7]
    for (int step = 0; step < 7; ++step) {
        int outSel = (step & 1) ? 2 : 1;           // bufA, bufB, bufA, ...
        gemm_splitk<<<dim3(NN / BN, NN / BM, NSPLIT), 256>>>(inSel, weight, S);
        reduce_add<<<NN2 / 4 / 256, 256>>>(weight + (size_t)(6 - step) * NN2, outSel);
        inSel = outSel;
    }
    // 7 steps (odd count) -> final operator lands in g_bufA
    gemm_out<<<dim3(NB / 2, NN / BM), 256>>>(nodes, out);
}

// round 3
// speedup vs baseline: 1.4549x; 1.4549x over previous
#include <cuda_runtime.h>
#include <cuda_bf16.h>
#include <cstdint>

#define NN   1024
#define NN2  (NN * NN)
#define BD   64
#define NB   128
#define ROWB 80          // 64B of k-data per row + 16B pad -> conflict-free ldmatrix

// ============================================================================
// Device global scratch (allocation-free rule)
// ============================================================================
__device__ __align__(16) __nv_bfloat16 g_St_hi[NN2];
__device__ __align__(16) __nv_bfloat16 g_St_lo[NN2];
__device__ __align__(16) __nv_bfloat16 g_Ta_hi[NN2];
__device__ __align__(16) __nv_bfloat16 g_Ta_lo[NN2];
__device__ __align__(16) __nv_bfloat16 g_Tb_hi[NN2];
__device__ __align__(16) __nv_bfloat16 g_Tb_lo[NN2];
__device__ __align__(16) __nv_bfloat16 g_Xt_hi[(size_t)NB * BD * NN];
__device__ __align__(16) __nv_bfloat16 g_Xt_lo[(size_t)NB * BD * NN];

// ============================================================================
// PTX helpers (all baseline sm_80-class: legal under compute_103)
// ============================================================================
__device__ __forceinline__ uint32_t smem_to_u32(const void* p) {
    uint32_t a;
    asm("{ .reg .u64 t; cvta.to.shared.u64 t, %1; cvt.u32.u64 %0, t; }"
        : "=r"(a) : "l"(p));
    return a;
}
__device__ __forceinline__ void cp16(uint32_t s, const void* g) {
    asm volatile("cp.async.cg.shared.global [%0], [%1], 16;" :: "r"(s), "l"(g));
}
#define CP_COMMIT() asm volatile("cp.async.commit_group;" ::: "memory")
#define CP_WAIT(n)  asm volatile("cp.async.wait_group %0;" :: "n"(n) : "memory")

__device__ __forceinline__ void ldsm4(uint32_t& r0, uint32_t& r1,
                                      uint32_t& r2, uint32_t& r3, uint32_t a) {
    asm volatile("ldmatrix.sync.aligned.m8n8.x4.shared.b16 {%0,%1,%2,%3}, [%4];"
                 : "=r"(r0), "=r"(r1), "=r"(r2), "=r"(r3) : "r"(a));
}
__device__ __forceinline__ void mma16816(float* c, const uint32_t* a,
                                         uint32_t b0, uint32_t b1) {
    asm volatile(
        "mma.sync.aligned.m16n8k16.row.col.f32.bf16.bf16.f32 "
        "{%0,%1,%2,%3}, {%4,%5,%6,%7}, {%8,%9}, {%0,%1,%2,%3};"
        : "+f"(c[0]), "+f"(c[1]), "+f"(c[2]), "+f"(c[3])
        : "r"(a[0]), "r"(a[1]), "r"(a[2]), "r"(a[3]), "r"(b0), "r"(b1));
}

__device__ __forceinline__ void split_bf16(float v, __nv_bfloat16& h, __nv_bfloat16& l) {
    h = __float2bfloat16(v);
    l = __float2bfloat16(v - __bfloat162float(h));
}

// ============================================================================
// Converts
// ============================================================================
// St[n][k] = split(S[k][n])
__global__ __launch_bounds__(256) void convert_S(const float* __restrict__ S) {
    __shared__ float tile[64][65];
    int k0 = blockIdx.x * 64, n0 = blockIdx.y * 64;
    for (int idx = threadIdx.x; idx < 64 * 64; idx += 256) {
        int r = idx >> 6, c = idx & 63;
        tile[r][c] = S[(size_t)(k0 + r) * NN + n0 + c];
    }
    __syncthreads();
    for (int idx = threadIdx.x; idx < 64 * 64; idx += 256) {
        int r = idx >> 6, c = idx & 63;
        __nv_bfloat16 h, l; split_bf16(tile[c][r], h, l);
        size_t o = (size_t)(n0 + r) * NN + k0 + c;
        g_St_hi[o] = h; g_St_lo[o] = l;
    }
}
// Xt[b][d][k] = split(X[b][k][d])
__global__ __launch_bounds__(256) void convert_X(const float* __restrict__ X) {
    __shared__ float tile[64][65];
    int k0 = blockIdx.x * 64, b = blockIdx.y;
    for (int idx = threadIdx.x; idx < 64 * 64; idx += 256) {
        int r = idx >> 6, c = idx & 63;
        tile[r][c] = X[((size_t)b * NN + k0 + r) * BD + c];
    }
    __syncthreads();
    for (int idx = threadIdx.x; idx < 64 * 64; idx += 256) {
        int r = idx >> 6, c = idx & 63;
        __nv_bfloat16 h, l; split_bf16(tile[c][r], h, l);
        size_t o = ((size_t)b * BD + r) * NN + k0 + c;
        g_Xt_hi[o] = h; g_Xt_lo[o] = l;
    }
}
// Ta = split(W7)
__global__ __launch_bounds__(256) void convert_init(const float* __restrict__ W7) {
    size_t i = (size_t)blockIdx.x * 256 + threadIdx.x;
    __nv_bfloat16 h, l; split_bf16(W7[i], h, l);
    g_Ta_hi[i] = h; g_Ta_lo[i] = l;
}

// ============================================================================
// gemm_horner: C[64x128] = T @ S (Kext = 3072 split-precision) + Wk
// grid (8, 16) = 128 CTAs, 256 threads, warps 2(M) x 4(N), warp tile 32x32.
// ============================================================================
#define H_ABYTES (64 * ROWB)
#define H_BBYTES (128 * ROWB)
#define H_STG    (H_ABYTES + H_BBYTES)

__global__ __launch_bounds__(256)
void gemm_horner(int inSel, const float* __restrict__ weight, int wkIdx) {
    __shared__ __align__(16) char smem[2 * H_STG];
    const int tid  = threadIdx.x;
    const int lane = tid & 31, w = tid >> 5;
    const int wm   = (w >> 2) * 32;       // 0, 32
    const int wn   = (w & 3) * 32;        // 0..96
    const int row0 = blockIdx.y * 64;
    const int col0 = blockIdx.x * 128;
    const uint32_t sbase = smem_to_u32(smem);

    const __nv_bfloat16* Ah = inSel ? g_Tb_hi : g_Ta_hi;
    const __nv_bfloat16* Al = inSel ? g_Tb_lo : g_Ta_lo;
    __nv_bfloat16* Oh = inSel ? g_Ta_hi : g_Tb_hi;
    __nv_bfloat16* Ol = inSel ? g_Ta_lo : g_Tb_lo;

    auto loadStage = [&](int s, int buf) {
        const int kk  = s * 32;
        const int seg = kk >> 10;
        const int k   = kk & 1023;
        const __nv_bfloat16* Ap = (seg < 2) ? Ah : Al;
        const __nv_bfloat16* Bp = (seg == 1) ? g_St_lo : g_St_hi;
        const uint32_t sA = sbase + buf * H_STG;
        const uint32_t sB = sA + H_ABYTES;
        { int r = tid >> 2, c = tid & 3;
          cp16(sA + r * ROWB + c * 16, Ap + (size_t)(row0 + r) * NN + k + c * 8); }
        #pragma unroll
        for (int i = 0; i < 2; ++i) {
            int idx = tid + i * 256, r = idx >> 2, c = idx & 3;
            cp16(sB + r * ROWB + c * 16, Bp + (size_t)(col0 + r) * NN + k + c * 8);
        }
        CP_COMMIT();
    };

    float acc[2][4][4] = {};
    loadStage(0, 0);

    for (int s = 0; s < 96; ++s) {
        if (s + 1 < 96) { loadStage(s + 1, (s + 1) & 1); CP_WAIT(1); }
        else            { CP_WAIT(0); }
        __syncthreads();

        const uint32_t sA = sbase + (s & 1) * H_STG;
        const uint32_t sB = sA + H_ABYTES;
        #pragma unroll
        for (int k16 = 0; k16 < 2; ++k16) {
            uint32_t a[2][4], b[2][4];
            #pragma unroll
            for (int mt = 0; mt < 2; ++mt)
                ldsm4(a[mt][0], a[mt][1], a[mt][2], a[mt][3],
                      sA + (uint32_t)(wm + mt * 16 + (lane & 15)) * ROWB
                         + (uint32_t)(k16 * 2 + (lane >> 4)) * 16);
            #pragma unroll
            for (int p = 0; p < 2; ++p)
                ldsm4(b[p][0], b[p][1], b[p][2], b[p][3],
                      sB + (uint32_t)(wn + p * 16 + ((lane >> 4) << 3) + (lane & 7)) * ROWB
                         + (uint32_t)(k16 * 2 + ((lane >> 3) & 1)) * 16);
            #pragma unroll
            for (int mt = 0; mt < 2; ++mt)
                #pragma unroll
                for (int nt = 0; nt < 4; ++nt)
                    mma16816(acc[mt][nt], a[mt],
                             b[nt >> 1][(nt & 1) * 2], b[nt >> 1][(nt & 1) * 2 + 1]);
        }
        __syncthreads();
    }

    // epilogue: + Wk, split, store
    const int g  = lane >> 2;
    const int i2 = (lane & 3) * 2;
    const float* wp = weight + (size_t)wkIdx * NN2;
    #pragma unroll
    for (int mt = 0; mt < 2; ++mt)
        #pragma unroll
        for (int nt = 0; nt < 4; ++nt) {
            const int m0 = row0 + wm + mt * 16 + g;
            const int n  = col0 + wn + nt * 8 + i2;
            float2 w0 = *(const float2*)(wp + (size_t)m0 * NN + n);
            float2 w1 = *(const float2*)(wp + (size_t)(m0 + 8) * NN + n);
            float v00 = acc[mt][nt][0] + w0.x, v01 = acc[mt][nt][1] + w0.y;
            float v10 = acc[mt][nt][2] + w1.x, v11 = acc[mt][nt][3] + w1.y;
            __nv_bfloat16 h0, l0, h1, l1;
            __nv_bfloat162 ph, pl;
            split_bf16(v00, h0, l0); split_bf16(v01, h1, l1);
            ph.x = h0; ph.y = h1; pl.x = l0; pl.y = l1;
            *(__nv_bfloat162*)(Oh + (size_t)m0 * NN + n) = ph;
            *(__nv_bfloat162*)(Ol + (size_t)m0 * NN + n) = pl;
            split_bf16(v10, h0, l0); split_bf16(v11, h1, l1);
            ph.x = h0; ph.y = h1; pl.x = l0; pl.y = l1;
            *(__nv_bfloat162*)(Oh + (size_t)(m0 + 8) * NN + n) = ph;
            *(__nv_bfloat162*)(Ol + (size_t)(m0 + 8) * NN + n) = pl;
        }
}

// ============================================================================
// gemm_final: out[b] = T @ X[b], 2 batches per CTA (tile 128 x 128).
// grid (64, 8) = 512 CTAs, warps 2(M) x 4(N), warp tile 64x32.
// ============================================================================
#define F_ABYTES (128 * ROWB)
#define F_BBYTES (128 * ROWB)
#define F_STG    (F_ABYTES + F_BBYTES)

__global__ __launch_bounds__(256)
void gemm_final(float* __restrict__ out) {
    __shared__ __align__(16) char smem[2 * F_STG];
    const int tid  = threadIdx.x;
    const int lane = tid & 31, w = tid >> 5;
    const int wm   = (w >> 2) * 64;       // 0, 64
    const int wn   = (w & 3) * 32;
    const int b0   = blockIdx.x * 2;
    const int row0 = blockIdx.y * 128;
    const uint32_t sbase = smem_to_u32(smem);

    auto loadStage = [&](int s, int buf) {
        const int kk  = s * 32;
        const int seg = kk >> 10;
        const int k   = kk & 1023;
        const __nv_bfloat16* Ap = (seg < 2) ? g_Tb_hi : g_Tb_lo;
        const __nv_bfloat16* Bp = (seg == 1) ? g_Xt_lo : g_Xt_hi;
        const uint32_t sA = sbase + buf * F_STG;
        const uint32_t sB = sA + F_ABYTES;
        #pragma unroll
        for (int i = 0; i < 2; ++i) {
            int idx = tid + i * 256, r = idx >> 2, c = idx & 3;
            cp16(sA + r * ROWB + c * 16, Ap + (size_t)(row0 + r) * NN + k + c * 8);
        }
        #pragma unroll
        for (int i = 0; i < 2; ++i) {
            int idx = tid + i * 256, r = idx >> 2, c = idx & 3;
            int batch = b0 + (r >> 6), d = r & 63;
            cp16(sB + r * ROWB + c * 16,
                 Bp + ((size_t)batch * BD + d) * NN + k + c * 8);
        }
        CP_COMMIT();
    };

    float acc[4][4][4] = {};
    loadStage(0, 0);

    for (int s = 0; s < 96; ++s) {
        if (s + 1 < 96) { loadStage(s + 1, (s + 1) & 1); CP_WAIT(1); }
        else            { CP_WAIT(0); }
        __syncthreads();

        const uint32_t sA = sbase + (s & 1) * F_STG;
        const uint32_t sB = sA + F_ABYTES;
        #pragma unroll
        for (int k16 = 0; k16 < 2; ++k16) {
            uint32_t a[4][4], b[2][4];
            #pragma unroll
            for (int mt = 0; mt < 4; ++mt)
                ldsm4(a[mt][0], a[mt][1], a[mt][2], a[mt][3],
                      sA + (uint32_t)(wm + mt * 16 + (lane & 15)) * ROWB
                         + (uint32_t)(k16 * 2 + (lane >> 4)) * 16);
            #pragma unroll
            for (int p = 0; p < 2; ++p)
                ldsm4(b[p][0], b[p][1], b[p][2], b[p][3],
                      sB + (uint32_t)(wn + p * 16 + ((lane >> 4) << 3) + (lane & 7)) * ROWB
                         + (uint32_t)(k16 * 2 + ((lane >> 3) & 1)) * 16);
            #pragma unroll
            for (int mt = 0; mt < 4; ++mt)
                #pragma unroll
                for (int nt = 0; nt < 4; ++nt)
                    mma16816(acc[mt][nt], a[mt],
                             b[nt >> 1][(nt & 1) * 2], b[nt >> 1][(nt & 1) * 2 + 1]);
        }
        __syncthreads();
    }

    const int g  = lane >> 2;
    const int i2 = (lane & 3) * 2;
    #pragma unroll
    for (int mt = 0; mt < 4; ++mt)
        #pragma unroll
        for (int nt = 0; nt < 4; ++nt) {
            const int m0   = row0 + wm + mt * 16 + g;
            const int ncol = wn + nt * 8 + i2;
            const int batch = b0 + (ncol >> 6);
            const int d     = ncol & 63;
            float* o0 = out + ((size_t)batch * NN + m0) * BD + d;
            float* o1 = out + ((size_t)batch * NN + m0 + 8) * BD + d;
            *(float2*)o0 = make_float2(acc[mt][nt][0], acc[mt][nt][1]);
            *(float2*)o1 = make_float2(acc[mt][nt][2], acc[mt][nt][3]);
        }
}

// ============================================================================
// Host orchestration:
//   T = W7; for k = 6..0: T = T @ S + Wk;  out[b] = T @ X[b]
// ============================================================================
extern "C" void kernel_launch(void* const* d_in, const int* in_sizes, int n_in,
                              void* d_out, int out_size) {
    const float* nodes  = (const float*)d_in[0];   // [128, 1024, 64]
    const float* weight = (const float*)d_in[1];   // [8, 1024, 1024]
    const float* S      = (const float*)d_in[2];   // [1024, 1024]
    float* out = (float*)d_out;                    // [128, 1024, 64]

    convert_S   <<<dim3(16, 16), 256>>>(S);
    convert_X   <<<dim3(16, NB), 256>>>(nodes);
    convert_init<<<NN2 / 256, 256>>>(weight + (size_t)7 * NN2);

    for (int step = 0; step < 7; ++step) {
        int inSel = step & 1;  // 0: read Ta, write Tb; 1: read Tb, write Ta
        gemm_horner<<<dim3(8, 16), 256>>>(inSel, weight, 6 - step);
    }
    // 7 steps -> final operator in Tb
    gemm_final<<<dim3(64, 8), 256>>>(out);
}

// round 4
// speedup vs baseline: 1.7537x; 1.2054x over previous
#include <cuda_runtime.h>
#include <cuda_bf16.h>
#include <cstdint>

#define NN   1024
#define NN2  (NN * NN)
#define BD   64
#define NB   128
#define ROWB 80          // 64B of k-data per row + 16B pad -> conflict-free ldmatrix

// ============================================================================
// Device global scratch (allocation-free rule)
// ============================================================================
__device__ __align__(16) __nv_bfloat16 g_St_hi[NN2];
__device__ __align__(16) __nv_bfloat16 g_St_lo[NN2];
__device__ __align__(16) __nv_bfloat16 g_Ta_hi[NN2];
__device__ __align__(16) __nv_bfloat16 g_Ta_lo[NN2];
__device__ __align__(16) __nv_bfloat16 g_Tb_hi[NN2];
__device__ __align__(16) __nv_bfloat16 g_Tb_lo[NN2];
__device__ __align__(16) __nv_bfloat16 g_Xt_hi[(size_t)NB * BD * NN];
__device__ __align__(16) __nv_bfloat16 g_Xt_lo[(size_t)NB * BD * NN];

// ============================================================================
// PTX helpers (baseline sm_80-class, legal under compute_103)
// ============================================================================
__device__ __forceinline__ uint32_t smem_to_u32(const void* p) {
    uint32_t a;
    asm("{ .reg .u64 t; cvta.to.shared.u64 t, %1; cvt.u32.u64 %0, t; }"
        : "=r"(a) : "l"(p));
    return a;
}
__device__ __forceinline__ void cp16(uint32_t s, const void* g) {
    asm volatile("cp.async.cg.shared.global [%0], [%1], 16;" :: "r"(s), "l"(g));
}
#define CP_COMMIT() asm volatile("cp.async.commit_group;" ::: "memory")
#define CP_WAIT(n)  asm volatile("cp.async.wait_group %0;" :: "n"(n) : "memory")

__device__ __forceinline__ void ldsm4(uint32_t& r0, uint32_t& r1,
                                      uint32_t& r2, uint32_t& r3, uint32_t a) {
    asm volatile("ldmatrix.sync.aligned.m8n8.x4.shared.b16 {%0,%1,%2,%3}, [%4];"
                 : "=r"(r0), "=r"(r1), "=r"(r2), "=r"(r3) : "r"(a));
}
__device__ __forceinline__ void mma16816(float* c, const uint32_t* a,
                                         uint32_t b0, uint32_t b1) {
    asm volatile(
        "mma.sync.aligned.m16n8k16.row.col.f32.bf16.bf16.f32 "
        "{%0,%1,%2,%3}, {%4,%5,%6,%7}, {%8,%9}, {%0,%1,%2,%3};"
        : "+f"(c[0]), "+f"(c[1]), "+f"(c[2]), "+f"(c[3])
        : "r"(a[0]), "r"(a[1]), "r"(a[2]), "r"(a[3]), "r"(b0), "r"(b1));
}

__device__ __forceinline__ void split_bf16(float v, __nv_bfloat16& h, __nv_bfloat16& l) {
    h = __float2bfloat16(v);
    l = __float2bfloat16(v - __bfloat162float(h));
}

// ============================================================================
// Converts
// ============================================================================
// St[n][k] = split(S[k][n])
__global__ __launch_bounds__(256) void convert_S(const float* __restrict__ S) {
    __shared__ float tile[64][65];
    int k0 = blockIdx.x * 64, n0 = blockIdx.y * 64;
    for (int idx = threadIdx.x; idx < 64 * 64; idx += 256) {
        int r = idx >> 6, c = idx & 63;
        tile[r][c] = S[(size_t)(k0 + r) * NN + n0 + c];
    }
    __syncthreads();
    for (int idx = threadIdx.x; idx < 64 * 64; idx += 256) {
        int r = idx >> 6, c = idx & 63;
        __nv_bfloat16 h, l; split_bf16(tile[c][r], h, l);
        size_t o = (size_t)(n0 + r) * NN + k0 + c;
        g_St_hi[o] = h; g_St_lo[o] = l;
    }
}
// Xt[b][d][k] = split(X[b][k][d])
__global__ __launch_bounds__(256) void convert_X(const float* __restrict__ X) {
    __shared__ float tile[64][65];
    int k0 = blockIdx.x * 64, b = blockIdx.y;
    for (int idx = threadIdx.x; idx < 64 * 64; idx += 256) {
        int r = idx >> 6, c = idx & 63;
        tile[r][c] = X[((size_t)b * NN + k0 + r) * BD + c];
    }
    __syncthreads();
    for (int idx = threadIdx.x; idx < 64 * 64; idx += 256) {
        int r = idx >> 6, c = idx & 63;
        __nv_bfloat16 h, l; split_bf16(tile[c][r], h, l);
        size_t o = ((size_t)b * BD + r) * NN + k0 + c;
        g_Xt_hi[o] = h; g_Xt_lo[o] = l;
    }
}
// Ta = split(W7)
__global__ __launch_bounds__(256) void convert_init(const float* __restrict__ W7) {
    size_t i = (size_t)blockIdx.x * 256 + threadIdx.x;
    __nv_bfloat16 h, l; split_bf16(W7[i], h, l);
    g_Ta_hi[i] = h; g_Ta_lo[i] = l;
}

// ============================================================================
// gemm_horner: C[64x64] = T @ S (Kext = 3072 split-precision) + Wk
// grid (16, 16) = 256 CTAs, 128 threads (warps 2Mx2N, warp tile 32x32).
// 4-stage cp.async pipeline, BK=32, one __syncthreads per K-step.
// ============================================================================
#define H_STG_BYTES (128 * ROWB)   // 64 A rows + 64 B rows = 10240 B/stage
#define H_STAGES    4

__global__ __launch_bounds__(128)
void gemm_horner(int inSel, const float* __restrict__ weight, int wkIdx) {
    __shared__ __align__(16) char smem[H_STAGES * H_STG_BYTES];   // 40 KB
    const int tid  = threadIdx.x;
    const int lane = tid & 31, w = tid >> 5;
    const int wm   = (w >> 1) * 32;
    const int wn   = (w & 1) * 32;
    const int row0 = blockIdx.y * 64;
    const int col0 = blockIdx.x * 64;
    const uint32_t sbase = smem_to_u32(smem);

    const __nv_bfloat16* Ah = inSel ? g_Tb_hi : g_Ta_hi;
    const __nv_bfloat16* Al = inSel ? g_Tb_lo : g_Ta_lo;
    __nv_bfloat16* Oh = inSel ? g_Ta_hi : g_Tb_hi;
    __nv_bfloat16* Ol = inSel ? g_Ta_lo : g_Tb_lo;

    auto loadStage = [&](int s, int slot) {
        const int kk  = s * 32;
        const int seg = kk >> 10;
        const int k   = kk & 1023;
        const __nv_bfloat16* Ap = (seg < 2) ? Ah : Al;
        const __nv_bfloat16* Bp = (seg == 1) ? g_St_lo : g_St_hi;
        const uint32_t base = sbase + slot * H_STG_BYTES;
        #pragma unroll
        for (int i = 0; i < 4; ++i) {
            int idx = tid + i * 128;           // 0..511
            int r = idx >> 2, c = idx & 3;
            const __nv_bfloat16* src = (r < 64)
                ? Ap + (size_t)(row0 + r) * NN + k + c * 8
                : Bp + (size_t)(col0 + r - 64) * NN + k + c * 8;
            cp16(base + r * ROWB + c * 16, src);
        }
        CP_COMMIT();
    };

    float acc[2][4][4] = {};
    loadStage(0, 0); loadStage(1, 1); loadStage(2, 2);

    for (int s = 0; s < 96; ++s) {
        CP_WAIT(2);
        __syncthreads();
        const uint32_t sA = sbase + (s & 3) * H_STG_BYTES;
        const uint32_t sB = sA + 64 * ROWB;

        if (s + 3 < 96) loadStage(s + 3, (s + 3) & 3);
        else            CP_COMMIT();

        #pragma unroll
        for (int k16 = 0; k16 < 2; ++k16) {
            uint32_t a[2][4], b[2][4];
            #pragma unroll
            for (int mt = 0; mt < 2; ++mt)
                ldsm4(a[mt][0], a[mt][1], a[mt][2], a[mt][3],
                      sA + (uint32_t)(wm + mt * 16 + (lane & 15)) * ROWB
                         + (uint32_t)(k16 * 2 + (lane >> 4)) * 16);
            #pragma unroll
            for (int p = 0; p < 2; ++p)
                ldsm4(b[p][0], b[p][1], b[p][2], b[p][3],
                      sB + (uint32_t)(wn + p * 16 + ((lane >> 4) << 3) + (lane & 7)) * ROWB
                         + (uint32_t)(k16 * 2 + ((lane >> 3) & 1)) * 16);
            #pragma unroll
            for (int mt = 0; mt < 2; ++mt)
                #pragma unroll
                for (int nt = 0; nt < 4; ++nt)
                    mma16816(acc[mt][nt], a[mt],
                             b[nt >> 1][(nt & 1) * 2], b[nt >> 1][(nt & 1) * 2 + 1]);
        }
    }

    // epilogue: + Wk, split, store
    const int g  = lane >> 2;
    const int i2 = (lane & 3) * 2;
    const float* wp = weight + (size_t)wkIdx * NN2;
    #pragma unroll
    for (int mt = 0; mt < 2; ++mt)
        #pragma unroll
        for (int nt = 0; nt < 4; ++nt) {
            const int m0 = row0 + wm + mt * 16 + g;
            const int n  = col0 + wn + nt * 8 + i2;
            float2 w0 = *(const float2*)(wp + (size_t)m0 * NN + n);
            float2 w1 = *(const float2*)(wp + (size_t)(m0 + 8) * NN + n);
            float v00 = acc[mt][nt][0] + w0.x, v01 = acc[mt][nt][1] + w0.y;
            float v10 = acc[mt][nt][2] + w1.x, v11 = acc[mt][nt][3] + w1.y;
            __nv_bfloat16 h0, l0, h1, l1;
            __nv_bfloat162 ph, pl;
            split_bf16(v00, h0, l0); split_bf16(v01, h1, l1);
            ph.x = h0; ph.y = h1; pl.x = l0; pl.y = l1;
            *(__nv_bfloat162*)(Oh + (size_t)m0 * NN + n) = ph;
            *(__nv_bfloat162*)(Ol + (size_t)m0 * NN + n) = pl;
            split_bf16(v10, h0, l0); split_bf16(v11, h1, l1);
            ph.x = h0; ph.y = h1; pl.x = l0; pl.y = l1;
            *(__nv_bfloat162*)(Oh + (size_t)(m0 + 8) * NN + n) = ph;
            *(__nv_bfloat162*)(Ol + (size_t)(m0 + 8) * NN + n) = pl;
        }
}

// ============================================================================
// gemm_final: out[b] = T @ X[b], 2 batches per CTA (tile 128 x 128).
// grid (64, 8) = 512 CTAs, 256 threads, warps 2Mx4N, warp tile 64x32.
// 4-stage cp.async pipeline (dynamic smem, 80KB).
// ============================================================================
#define F_STG_BYTES (256 * ROWB)   // 128 A rows + 128 B rows = 20480 B/stage
#define F_STAGES    4
#define F_SMEM      (F_STAGES * F_STG_BYTES)

__global__ __launch_bounds__(256)
void gemm_final(float* __restrict__ out) {
    extern __shared__ __align__(16) char fsm[];
    const int tid  = threadIdx.x;
    const int lane = tid & 31, w = tid >> 5;
    const int wm   = (w >> 2) * 64;
    const int wn   = (w & 3) * 32;
    const int b0   = blockIdx.x * 2;
    const int row0 = blockIdx.y * 128;
    const uint32_t sbase = smem_to_u32(fsm);

    auto loadStage = [&](int s, int slot) {
        const int kk  = s * 32;
        const int seg = kk >> 10;
        const int k   = kk & 1023;
        const __nv_bfloat16* Ap = (seg < 2) ? g_Tb_hi : g_Tb_lo;
        const __nv_bfloat16* Bp = (seg == 1) ? g_Xt_lo : g_Xt_hi;
        const uint32_t base = sbase + slot * F_STG_BYTES;
        #pragma unroll
        for (int i = 0; i < 4; ++i) {
            int idx = tid + i * 256;           // 0..1023
            int r = idx >> 2, c = idx & 3;
            const __nv_bfloat16* src;
            if (r < 128) {
                src = Ap + (size_t)(row0 + r) * NN + k + c * 8;
            } else {
                int rr = r - 128;
                int batch = b0 + (rr >> 6), d = rr & 63;
                src = Bp + ((size_t)batch * BD + d) * NN + k + c * 8;
            }
            cp16(base + r * ROWB + c * 16, src);
        }
        CP_COMMIT();
    };

    float acc[4][4][4] = {};
    loadStage(0, 0); loadStage(1, 1); loadStage(2, 2);

    for (int s = 0; s < 96; ++s) {
        CP_WAIT(2);
        __syncthreads();
        const uint32_t sA = sbase + (s & 3) * F_STG_BYTES;
        const uint32_t sB = sA + 128 * ROWB;

        if (s + 3 < 96) loadStage(s + 3, (s + 3) & 3);
        else            CP_COMMIT();

        #pragma unroll
        for (int k16 = 0; k16 < 2; ++k16) {
            uint32_t a[4][4], b[2][4];
            #pragma unroll
            for (int mt = 0; mt < 4; ++mt)
                ldsm4(a[mt][0], a[mt][1], a[mt][2], a[mt][3],
                      sA + (uint32_t)(wm + mt * 16 + (lane & 15)) * ROWB
                         + (uint32_t)(k16 * 2 + (lane >> 4)) * 16);
            #pragma unroll
            for (int p = 0; p < 2; ++p)
                ldsm4(b[p][0], b[p][1], b[p][2], b[p][3],
                      sB + (uint32_t)(wn + p * 16 + ((lane >> 4) << 3) + (lane & 7)) * ROWB
                         + (uint32_t)(k16 * 2 + ((lane >> 3) & 1)) * 16);
            #pragma unroll
            for (int mt = 0; mt < 4; ++mt)
                #pragma unroll
                for (int nt = 0; nt < 4; ++nt)
                    mma16816(acc[mt][nt], a[mt],
                             b[nt >> 1][(nt & 1) * 2], b[nt >> 1][(nt & 1) * 2 + 1]);
        }
    }

    const int g  = lane >> 2;
    const int i2 = (lane & 3) * 2;
    #pragma unroll
    for (int mt = 0; mt < 4; ++mt)
        #pragma unroll
        for (int nt = 0; nt < 4; ++nt) {
            const int m0   = row0 + wm + mt * 16 + g;
            const int ncol = wn + nt * 8 + i2;
            const int batch = b0 + (ncol >> 6);
            const int d     = ncol & 63;
            float* o0 = out + ((size_t)batch * NN + m0) * BD + d;
            float* o1 = out + ((size_t)batch * NN + m0 + 8) * BD + d;
            *(float2*)o0 = make_float2(acc[mt][nt][0], acc[mt][nt][1]);
            *(float2*)o1 = make_float2(acc[mt][nt][2], acc[mt][nt][3]);
        }
}

// ============================================================================
// Host orchestration:
//   T = W7; for k = 6..0: T = T @ S + Wk;  out[b] = T @ X[b]
// ============================================================================
extern "C" void kernel_launch(void* const* d_in, const int* in_sizes, int n_in,
                              void* d_out, int out_size) {
    const float* nodes  = (const float*)d_in[0];   // [128, 1024, 64]
    const float* weight = (const float*)d_in[1];   // [8, 1024, 1024]
    const float* S      = (const float*)d_in[2];   // [1024, 1024]
    float* out = (float*)d_out;                    // [128, 1024, 64]

    cudaFuncSetAttribute(gemm_final, cudaFuncAttributeMaxDynamicSharedMemorySize, F_SMEM);

    convert_S   <<<dim3(16, 16), 256>>>(S);
    convert_X   <<<dim3(16, NB), 256>>>(nodes);
    convert_init<<<NN2 / 256, 256>>>(weight + (size_t)7 * NN2);

    for (int step = 0; step < 7; ++step) {
        int inSel = step & 1;  // 0: read Ta, write Tb; 1: read Tb, write Ta
        gemm_horner<<<dim3(16, 16), 128>>>(inSel, weight, 6 - step);
    }
    // 7 steps -> final operator in Tb
    gemm_final<<<dim3(64, 8), 256, F_SMEM>>>(out);
}